// round 13
// baseline (speedup 1.0000x reference)
#include <cuda_runtime.h>
#include <cuda_bf16.h>

#define NN 4096
#define CC 128
#define NC (NN*CC)
#define NBR_CAP 512

// Scratch (device globals: allocation-free per harness rules)
__device__ float         g_q[NC];     // q fp32
__device__ __nv_bfloat16 g_kh[NC];    // k bf16
__device__ __nv_bfloat16 g_vh[NC];    // v bf16
__device__ float         g_attn[NC];  // attention output before out-proj
__device__ unsigned      g_mask[NC];  // 4096x4096 adjacency bitmask
__device__ unsigned      g_odd_or;    // edge-index dtype detection flag

// ---------------------------------------------------------------------------
// packed f32x2 helpers (FFMA2 only reachable via PTX fma.rn.f32x2)
// ---------------------------------------------------------------------------
__device__ __forceinline__ unsigned long long pk2(float x) {
    unsigned long long r;
    asm("mov.b64 %0, {%1, %1};" : "=l"(r) : "f"(x));
    return r;
}
__device__ __forceinline__ void fma2(unsigned long long& d,
                                     unsigned long long a,
                                     unsigned long long b) {
    asm("fma.rn.f32x2 %0, %1, %2, %0;" : "+l"(d) : "l"(a), "l"(b));
}
__device__ __forceinline__ float2 upk(unsigned long long v) {
    float2 f;
    asm("mov.b64 {%0, %1}, %2;" : "=f"(f.x), "=f"(f.y) : "l"(v));
    return f;
}

// ---------------------------------------------------------------------------
// 1) prep: clear mask + detect edge dtype (odd 32-bit words OR==0 -> int64)
// ---------------------------------------------------------------------------
__global__ void prep_kernel(const unsigned* __restrict__ w, int n2) {
    int i = blockIdx.x * blockDim.x + threadIdx.x;
    if (i == 0) g_odd_or = 0u;
    int stride = gridDim.x * blockDim.x;
    uint4 z = {0u, 0u, 0u, 0u};
    for (int j = i; j < NC / 4; j += stride) ((uint4*)g_mask)[j] = z;
    unsigned v = 0;
    for (int j = i; j < (n2 >> 1); j += stride) v |= w[2 * j + 1];
    #pragma unroll
    for (int o = 16; o; o >>= 1) v |= __shfl_xor_sync(0xffffffffu, v, o);
    if ((threadIdx.x & 31) == 0 && v) atomicOr(&g_odd_or, v);
}

__global__ void scatter_kernel(const void* __restrict__ ei_raw, int E) {
    int e = blockIdx.x * blockDim.x + threadIdx.x;
    if (e >= E) return;
    int r, c;
    if (g_odd_or == 0u) {  // int64 layout
        const long long* ei = (const long long*)ei_raw;
        r = (int)ei[e];
        c = (int)ei[E + e];
    } else {               // int32 layout
        const int* ei = (const int*)ei_raw;
        r = ei[e];
        c = ei[E + e];
    }
    if ((unsigned)r < NN && (unsigned)c < NN)
        atomicOr(&g_mask[(r << 7) + (c >> 5)], 1u << (c & 31));
}

// ---------------------------------------------------------------------------
// 2) fp32 GEMM core (BM=32, BN=128, BK=32, 256 thr, 4x4 tile, f32x2 FFMA)
//    MODE 0: fp32 out + bias            (q)
//    MODE 1: bf16 out + bias            (k, v)
//    MODE 2: fp32 + bias + res + fused LayerNorm -> out  (final)
// ---------------------------------------------------------------------------
template <int MODE>
__device__ __forceinline__ void gemm_core(const float* __restrict__ A,
                                          const float* __restrict__ W,
                                          const float* __restrict__ bias,
                                          const float* __restrict__ res,
                                          const float* __restrict__ gamma,
                                          const float* __restrict__ beta,
                                          float* __restrict__ out32,
                                          __nv_bfloat16* __restrict__ out16) {
    __shared__ float As[32][33];
    __shared__ float Bs[32][132];
    const int n0 = blockIdx.x * 32;
    const int t  = threadIdx.x;
    const int tn = t & 31;
    const int tm = t >> 5;
    const int kk = t & 31;
    const int rr = t >> 5;
    unsigned long long acc[4][2];   // 4 rows x 2 col-pairs (packed f32x2)
    #pragma unroll
    for (int i = 0; i < 4; i++) { acc[i][0] = 0ull; acc[i][1] = 0ull; }

    for (int k0 = 0; k0 < CC; k0 += 32) {
        #pragma unroll
        for (int p = 0; p < 4; p++)
            As[kk][rr + p*8] = A[(n0 + rr + p*8)*CC + k0 + kk];
        #pragma unroll
        for (int p = 0; p < 16; p++)
            Bs[kk][rr + p*8] = W[(rr + p*8)*CC + k0 + kk];
        __syncthreads();
        #pragma unroll
        for (int q = 0; q < 32; q++) {
            ulonglong2 bp = *(const ulonglong2*)&Bs[q][tn*4];
            #pragma unroll
            for (int i = 0; i < 4; i++) {
                unsigned long long ap = pk2(As[q][tm*4 + i]);  // warp-uniform bcast
                fma2(acc[i][0], ap, bp.x);
                fma2(acc[i][1], ap, bp.y);
            }
        }
        __syncthreads();
    }

    float4 bb = *(const float4*)&bias[tn*4];
    #pragma unroll
    for (int i = 0; i < 4; i++) {
        int row = n0 + tm*4 + i;
        float2 u0 = upk(acc[i][0]);
        float2 u1 = upk(acc[i][1]);
        float4 o;
        o.x = u0.x + bb.x;
        o.y = u0.y + bb.y;
        o.z = u1.x + bb.z;
        o.w = u1.y + bb.w;
        if (MODE == 0) {
            *(float4*)&out32[row*CC + tn*4] = o;
        } else if (MODE == 1) {
            __nv_bfloat162 h0 = {__float2bfloat16_rn(o.x), __float2bfloat16_rn(o.y)};
            __nv_bfloat162 h1 = {__float2bfloat16_rn(o.z), __float2bfloat16_rn(o.w)};
            *(__nv_bfloat162*)&out16[row*CC + tn*4]     = h0;
            *(__nv_bfloat162*)&out16[row*CC + tn*4 + 2] = h1;
        } else {
            float4 r4 = *(const float4*)&res[row*CC + tn*4];
            o.x += r4.x; o.y += r4.y; o.z += r4.z; o.w += r4.w;
            float s  = o.x + o.y + o.z + o.w;
            float s2 = o.x*o.x + o.y*o.y + o.z*o.z + o.w*o.w;
            #pragma unroll
            for (int sh = 16; sh; sh >>= 1) {
                s  += __shfl_xor_sync(0xffffffffu, s,  sh);
                s2 += __shfl_xor_sync(0xffffffffu, s2, sh);
            }
            float mu  = s * (1.f / CC);
            float var = s2 * (1.f / CC) - mu * mu;
            float rs  = rsqrtf(var + 1e-5f);
            float4 g = *(const float4*)&gamma[tn*4];
            float4 b = *(const float4*)&beta[tn*4];
            float4 o4;
            o4.x = (o.x - mu) * rs * g.x + b.x;
            o4.y = (o.y - mu) * rs * g.y + b.y;
            o4.z = (o.z - mu) * rs * g.z + b.z;
            o4.w = (o.w - mu) * rs * g.w + b.w;
            *(float4*)&out32[row*CC + tn*4] = o4;
        }
    }
}

__global__ __launch_bounds__(256) void qkv_gemm_kernel(
        const float* __restrict__ x,
        const float* __restrict__ wq, const float* __restrict__ wk, const float* __restrict__ wv,
        const float* __restrict__ bq, const float* __restrict__ bk, const float* __restrict__ bv) {
    int which = blockIdx.y;
    if (which == 0)
        gemm_core<0>(x, wq, bq, nullptr, nullptr, nullptr, g_q, nullptr);
    else if (which == 1)
        gemm_core<1>(x, wk, bk, nullptr, nullptr, nullptr, nullptr, g_kh);
    else
        gemm_core<1>(x, wv, bv, nullptr, nullptr, nullptr, nullptr, g_vh);
}

__global__ __launch_bounds__(256) void out_ln_kernel(
        const float* __restrict__ wo, const float* __restrict__ bo,
        const float* __restrict__ x,
        const float* __restrict__ gamma, const float* __restrict__ beta,
        float* __restrict__ out) {
    gemm_core<2>(g_attn, wo, bo, x, gamma, beta, out, nullptr);
}

// ---------------------------------------------------------------------------
// 3) sparse attention: 64 threads/node, warp = 128B line = 2 heads.
//    Per instruction lanes 0-15 read 8B of row 2i, lanes 16-31 of row 2i+1
//    -> every LDG.64 covers exactly 2 full cache lines (minimal wavefronts,
//    no staging, no inter-warp sync in the main loop).
// ---------------------------------------------------------------------------
__global__ __launch_bounds__(64) void attn_kernel() {
    __shared__ int   nbr[NBR_CAP];
    __shared__ float ps[4][34];        // [head][row], pad 34 -> conflict-free
    __shared__ int   wsum2[2];
    __shared__ int   s_deg;
    const int n    = blockIdx.x;
    const int t    = threadIdx.x;      // 0..63
    const int lane = t & 31;
    const int wrp  = t >> 5;           // line index: warp w owns heads 2w,2w+1

    // --- build deduped neighbor list: thread scans 2 mask words ---
    unsigned w0 = g_mask[(n << 7) + 2*t];
    unsigned w1 = g_mask[(n << 7) + 2*t + 1];
    int c = __popc(w0) + __popc(w1);
    int inc = c;
    #pragma unroll
    for (int o = 1; o < 32; o <<= 1) {
        int v = __shfl_up_sync(0xffffffffu, inc, o);
        if (lane >= o) inc += v;
    }
    if (lane == 31) wsum2[wrp] = inc;
    __syncthreads();
    int off = ((wrp == 1) ? wsum2[0] : 0) + inc - c;
    int colb = t << 6;
    while (w0) {
        int b = __ffs(w0) - 1; w0 &= w0 - 1;
        if (off < NBR_CAP) nbr[off] = colb + b;
        off++;
    }
    while (w1) {
        int b = __ffs(w1) - 1; w1 &= w1 - 1;
        if (off < NBR_CAP) nbr[off] = colb + 32 + b;
        off++;
    }
    if (t == 63) s_deg = (off < NBR_CAP) ? off : NBR_CAP;
    __syncthreads();
    const int deg = s_deg;             // >= 1 (self loops guaranteed)

    // --- per-thread geometry ---
    const int hsel  = (lane >> 3) & 1; // head within line
    const int h2    = wrp << 1;        // first head of this line
    const int rsel  = lane >> 4;       // 0: even chunk-row, 1: odd
    const int sub16 = lane & 15;       // 8B fragment within line
    const __nv_bfloat16* Kb = g_kh + wrp*64 + sub16*4;
    const __nv_bfloat16* Vb = g_vh + wrp*64 + sub16*4;

    // q fragment (pre-scaled) in registers
    float4 q4 = *(const float4*)&g_q[n*CC + wrp*64 + sub16*4];
    const float sc = 0.17677669529663687f;  // 1/sqrt(32)
    float q0 = q4.x*sc, q1 = q4.y*sc, q2 = q4.z*sc, q3 = q4.w*sc;

    float M0 = -1e30f, M1 = -1e30f, l0 = 0.f, l1 = 0.f;
    float a0 = 0.f, a1 = 0.f, a2 = 0.f, a3 = 0.f;

    for (int j0 = 0; j0 < deg; j0 += 32) {
        const int nj = min(32, deg - j0);

        // ---- phase A: scores (2 rows x 2 heads per instruction) ----
        #pragma unroll
        for (int i = 0; i < 16; i++) {
            int r = 2*i + rsel;
            int m = nbr[min(j0 + r, deg - 1)];
            uint2 u = *(const uint2*)(Kb + m*CC);
            float2 f0 = __bfloat1622float2(*(__nv_bfloat162*)&u.x);
            float2 f1 = __bfloat1622float2(*(__nv_bfloat162*)&u.y);
            float sv = q0*f0.x + q1*f0.y + q2*f1.x + q3*f1.y;
            sv += __shfl_xor_sync(0xffffffffu, sv, 1);
            sv += __shfl_xor_sync(0xffffffffu, sv, 2);
            sv += __shfl_xor_sync(0xffffffffu, sv, 4);
            if ((lane & 7) == 0) ps[h2 + hsel][r] = sv;
        }
        __syncwarp();

        // ---- phase B: softmax for both heads, lane = row ----
        float s0 = (lane < nj) ? ps[h2][lane]     : -1e30f;
        float s1 = (lane < nj) ? ps[h2 + 1][lane] : -1e30f;
        float mx0 = s0, mx1 = s1;
        #pragma unroll
        for (int o = 16; o; o >>= 1) {
            mx0 = fmaxf(mx0, __shfl_xor_sync(0xffffffffu, mx0, o));
            mx1 = fmaxf(mx1, __shfl_xor_sync(0xffffffffu, mx1, o));
        }
        float Mn0 = fmaxf(M0, mx0), Mn1 = fmaxf(M1, mx1);
        float p0 = (lane < nj) ? __expf(s0 - Mn0) : 0.f;
        float p1 = (lane < nj) ? __expf(s1 - Mn1) : 0.f;
        ps[h2][lane]     = p0;
        ps[h2 + 1][lane] = p1;
        float su0 = p0, su1 = p1;
        #pragma unroll
        for (int o = 16; o; o >>= 1) {
            su0 += __shfl_xor_sync(0xffffffffu, su0, o);
            su1 += __shfl_xor_sync(0xffffffffu, su1, o);
        }
        float c0 = __expf(M0 - Mn0), c1 = __expf(M1 - Mn1);
        l0 = l0*c0 + su0;
        l1 = l1*c1 + su1;
        float cm = hsel ? c1 : c0;
        a0 *= cm; a1 *= cm; a2 *= cm; a3 *= cm;
        M0 = Mn0; M1 = Mn1;
        __syncwarp();

        // ---- phase C: weighted v accumulate (p=0 kills padded rows) ----
        #pragma unroll
        for (int i = 0; i < 16; i++) {
            int r = 2*i + rsel;
            int m = nbr[min(j0 + r, deg - 1)];
            uint2 u = *(const uint2*)(Vb + m*CC);
            float p = ps[h2 + hsel][r];
            float2 f0 = __bfloat1622float2(*(__nv_bfloat162*)&u.x);
            float2 f1 = __bfloat1622float2(*(__nv_bfloat162*)&u.y);
            a0 += p*f0.x; a1 += p*f0.y; a2 += p*f1.x; a3 += p*f1.y;
        }
        __syncwarp();   // ps reused next chunk
    }

    // merge even/odd-row partials (lanes l and l^16 hold same (head,dims))
    a0 += __shfl_xor_sync(0xffffffffu, a0, 16);
    a1 += __shfl_xor_sync(0xffffffffu, a1, 16);
    a2 += __shfl_xor_sync(0xffffffffu, a2, 16);
    a3 += __shfl_xor_sync(0xffffffffu, a3, 16);
    if (lane < 16) {
        float rl = 1.f / (hsel ? l1 : l0);
        float4 o = {a0*rl, a1*rl, a2*rl, a3*rl};
        *(float4*)&g_attn[n*CC + wrp*64 + sub16*4] = o;
    }
}

// ---------------------------------------------------------------------------
extern "C" void kernel_launch(void* const* d_in, const int* in_sizes, int n_in,
                              void* d_out, int out_size) {
    const float* x     = (const float*)d_in[0];
    const void*  ei    = d_in[1];
    const float* wq    = (const float*)d_in[2];
    const float* bq    = (const float*)d_in[3];
    const float* wk    = (const float*)d_in[4];
    const float* bk    = (const float*)d_in[5];
    const float* wv    = (const float*)d_in[6];
    const float* bv    = (const float*)d_in[7];
    const float* wo    = (const float*)d_in[8];
    const float* bo    = (const float*)d_in[9];
    const float* gamma = (const float*)d_in[10];
    const float* beta  = (const float*)d_in[11];
    float*       out   = (float*)d_out;
    const int n_elems = in_sizes[1];   // 2*E regardless of dtype
    const int E = n_elems / 2;

    prep_kernel<<<512, 256>>>((const unsigned*)ei, n_elems);
    scatter_kernel<<<(E + 255) / 256, 256>>>(ei, E);
    qkv_gemm_kernel<<<dim3(NN/32, 3), 256>>>(x, wq, wk, wv, bq, bk, bv);
    attn_kernel<<<NN, 64>>>();
    out_ln_kernel<<<NN/32, 256>>>(wo, bo, x, gamma, beta, out);
}

// round 15
// speedup vs baseline: 1.4221x; 1.4221x over previous
#include <cuda_runtime.h>
#include <cuda_bf16.h>
#include <cstdint>

#define NN 4096
#define CC 128
#define NC (NN*CC)
#define NBR_CAP 512

// Scratch (device globals: allocation-free per harness rules)
__device__ float         g_q[NC];        // q fp32
__device__ __nv_bfloat16 g_xh[NC];       // x bf16
__device__ __nv_bfloat16 g_kh[NC];       // k bf16
__device__ __nv_bfloat16 g_vh[NC];       // v bf16
__device__ __nv_bfloat16 g_ah[NC];       // attention output bf16
__device__ __nv_bfloat16 g_wh[4*CC*CC];  // wq|wk|wv|wo bf16
__device__ unsigned      g_mask[NC];     // 4096x4096 adjacency bitmask
__device__ unsigned      g_odd_or;       // edge-index dtype detection flag

__device__ __forceinline__ uint32_t smem_u32(const void* p) {
    uint32_t a;
    asm("{ .reg .u64 t; cvta.to.shared.u64 t, %1; cvt.u32.u64 %0, t; }"
        : "=r"(a) : "l"(p));
    return a;
}
__device__ __forceinline__ void ldm_x4(uint32_t addr, uint32_t r[4]) {
    asm volatile("ldmatrix.sync.aligned.m8n8.x4.shared.b16 {%0,%1,%2,%3}, [%4];"
                 : "=r"(r[0]), "=r"(r[1]), "=r"(r[2]), "=r"(r[3]) : "r"(addr));
}
__device__ __forceinline__ void mma_bf16(float c[4], const uint32_t a[4],
                                         uint32_t b0, uint32_t b1) {
    asm volatile(
        "mma.sync.aligned.m16n8k16.row.col.f32.bf16.bf16.f32 "
        "{%0,%1,%2,%3}, {%4,%5,%6,%7}, {%8,%9}, {%0,%1,%2,%3};"
        : "+f"(c[0]), "+f"(c[1]), "+f"(c[2]), "+f"(c[3])
        : "r"(a[0]), "r"(a[1]), "r"(a[2]), "r"(a[3]), "r"(b0), "r"(b1));
}

// ---------------------------------------------------------------------------
// 1) prep: clear mask + detect edge dtype (odd 32-bit words OR==0 -> int64)
// ---------------------------------------------------------------------------
__global__ void prep_kernel(const unsigned* __restrict__ w, int n2) {
    int i = blockIdx.x * blockDim.x + threadIdx.x;
    if (i == 0) g_odd_or = 0u;
    int stride = gridDim.x * blockDim.x;
    uint4 z = {0u, 0u, 0u, 0u};
    for (int j = i; j < NC / 4; j += stride) ((uint4*)g_mask)[j] = z;
    unsigned v = 0;
    for (int j = i; j < (n2 >> 1); j += stride) v |= w[2 * j + 1];
    #pragma unroll
    for (int o = 16; o; o >>= 1) v |= __shfl_xor_sync(0xffffffffu, v, o);
    if ((threadIdx.x & 31) == 0 && v) atomicOr(&g_odd_or, v);
}

__global__ void scatter_kernel(const void* __restrict__ ei_raw, int E) {
    int e = blockIdx.x * blockDim.x + threadIdx.x;
    if (e >= E) return;
    int r, c;
    if (g_odd_or == 0u) {  // int64 layout
        const long long* ei = (const long long*)ei_raw;
        r = (int)ei[e];
        c = (int)ei[E + e];
    } else {               // int32 layout
        const int* ei = (const int*)ei_raw;
        r = ei[e];
        c = ei[E + e];
    }
    if ((unsigned)r < NN && (unsigned)c < NN)
        atomicOr(&g_mask[(r << 7) + (c >> 5)], 1u << (c & 31));
}

// ---------------------------------------------------------------------------
// 1b) bf16 conversion: x (NC elems) then wq|wk|wv|wo (4 x 16384)
// ---------------------------------------------------------------------------
__global__ void cvt_kernel(const float* __restrict__ x,
                           const float* __restrict__ wq, const float* __restrict__ wk,
                           const float* __restrict__ wv, const float* __restrict__ wo) {
    int i = blockIdx.x * blockDim.x + threadIdx.x;   // one float4 per thread
    const float* src;
    uint2* dst;
    int idx;
    if (i < NC / 4) {
        src = x; idx = i; dst = (uint2*)g_xh;
    } else {
        int j = i - NC / 4;
        if (j >= 4 * CC * CC / 4) return;
        int which = j >> 12;                          // 4096 float4 per weight
        idx = j & 4095;
        src = (which == 0) ? wq : (which == 1) ? wk : (which == 2) ? wv : wo;
        dst = (uint2*)(g_wh + which * CC * CC);
    }
    float4 f = ((const float4*)src)[idx];
    __nv_bfloat162 h0 = {__float2bfloat16_rn(f.x), __float2bfloat16_rn(f.y)};
    __nv_bfloat162 h1 = {__float2bfloat16_rn(f.z), __float2bfloat16_rn(f.w)};
    uint2 u;
    u.x = *(unsigned*)&h0;
    u.y = *(unsigned*)&h1;
    dst[idx] = u;
}

// ---------------------------------------------------------------------------
// 2) bf16 mma.sync GEMM: D[64 x 128] tile = A[64 x 128] @ W[128 x 128]^T
//    128 threads, warp grid 2m x 2n, warp tile 32x64, m16n8k16 frags.
//    smem: As[64][136] bf16 @0, Ws[128][136] bf16 @17408  (272B rows,
//    ldmatrix conflict-free); MODE2 reuses base as Cs[64][132] f32.
//    MODE 0: fp32 out + bias (q); MODE 1: bf16 out + bias (k,v);
//    MODE 2: + residual + fused LayerNorm -> final out.
// ---------------------------------------------------------------------------
template <int MODE>
__device__ __forceinline__ void mma_gemm_body(
        const __nv_bfloat16* __restrict__ A,
        const __nv_bfloat16* __restrict__ W,
        const float* __restrict__ bias,
        const float* __restrict__ res,
        const float* __restrict__ gamma,
        const float* __restrict__ beta,
        float* __restrict__ out32,
        __nv_bfloat16* __restrict__ out16) {
    extern __shared__ char smem[];
    char* AsB = smem;             // As: 64 rows * 272B
    char* WsB = smem + 17408;     // Ws: 128 rows * 272B
    float* Cs = (float*)smem;     // MODE2: [64][132]

    const int t    = threadIdx.x;
    const int lane = t & 31;
    const int wid  = t >> 5;
    const int wm   = wid & 1;     // m half: rows 32*wm
    const int wn   = wid >> 1;    // n half: cols 64*wn
    const int n0   = blockIdx.x * 64;

    // stage A (64x128 bf16) and W (128x128 bf16), rows padded to 272B
    #pragma unroll
    for (int i = 0; i < 8; i++) {
        int idx = t + i * 128;            // 0..1023
        int row = idx >> 4, u = idx & 15;
        *(uint4*)(AsB + row * 272 + u * 16) = ((const uint4*)A)[(n0 + row) * 16 + u];
    }
    #pragma unroll
    for (int i = 0; i < 16; i++) {
        int idx = t + i * 128;            // 0..2047
        int row = idx >> 4, u = idx & 15;
        *(uint4*)(WsB + row * 272 + u * 16) = ((const uint4*)W)[row * 16 + u];
    }
    __syncthreads();

    const uint32_t asb = smem_u32(AsB);
    const uint32_t wsb = smem_u32(WsB);

    float c[2][8][4];
    #pragma unroll
    for (int im = 0; im < 2; im++)
        #pragma unroll
        for (int jn = 0; jn < 8; jn++)
            #pragma unroll
            for (int e = 0; e < 4; e++) c[im][jn][e] = 0.f;

    #pragma unroll
    for (int kk = 0; kk < 8; kk++) {
        const int k0 = kk * 16;
        uint32_t a[2][4], b[4][4];
        #pragma unroll
        for (int im = 0; im < 2; im++) {
            uint32_t addr = asb + (wm * 32 + im * 16 + (lane & 15)) * 272
                          + (k0 + ((lane >> 4) << 3)) * 2;
            ldm_x4(addr, a[im]);
        }
        #pragma unroll
        for (int jp = 0; jp < 4; jp++) {
            int nb  = wn * 64 + jp * 16;
            int row = nb + ((lane >> 4) << 3) + (lane & 7);
            int col = k0 + (((lane >> 3) & 1) << 3);
            ldm_x4(wsb + row * 272 + col * 2, b[jp]);
        }
        #pragma unroll
        for (int im = 0; im < 2; im++)
            #pragma unroll
            for (int jp = 0; jp < 4; jp++) {
                mma_bf16(c[im][2*jp],     a[im], b[jp][0], b[jp][1]);
                mma_bf16(c[im][2*jp + 1], a[im], b[jp][2], b[jp][3]);
            }
    }

    const int qm = lane >> 2;         // 0..7
    const int qn = (lane & 3) * 2;    // 0,2,4,6

    if (MODE == 2) {
        __syncthreads();              // done with staging; reuse as Cs
        #pragma unroll
        for (int im = 0; im < 2; im++)
            #pragma unroll
            for (int jn = 0; jn < 8; jn++) {
                int rl = wm * 32 + im * 16 + qm;
                int cl = wn * 64 + jn * 8 + qn;
                float2 bb = *(const float2*)&bias[cl];
                float2 r0 = *(const float2*)&res[(n0 + rl) * CC + cl];
                float2 r1 = *(const float2*)&res[(n0 + rl + 8) * CC + cl];
                Cs[rl * 132 + cl]           = c[im][jn][0] + bb.x + r0.x;
                Cs[rl * 132 + cl + 1]       = c[im][jn][1] + bb.y + r0.y;
                Cs[(rl + 8) * 132 + cl]     = c[im][jn][2] + bb.x + r1.x;
                Cs[(rl + 8) * 132 + cl + 1] = c[im][jn][3] + bb.y + r1.y;
            }
        __syncthreads();
        // LayerNorm: warp per 16 rows, lane = 4 cols
        #pragma unroll
        for (int r = 0; r < 16; r++) {
            int row = wid * 16 + r;
            float4 y = *(const float4*)&Cs[row * 132 + lane * 4];
            float s  = y.x + y.y + y.z + y.w;
            float s2 = y.x*y.x + y.y*y.y + y.z*y.z + y.w*y.w;
            #pragma unroll
            for (int o = 16; o; o >>= 1) {
                s  += __shfl_xor_sync(0xffffffffu, s,  o);
                s2 += __shfl_xor_sync(0xffffffffu, s2, o);
            }
            float mu  = s * (1.f / CC);
            float var = s2 * (1.f / CC) - mu * mu;
            float rs  = rsqrtf(var + 1e-5f);
            float4 g = *(const float4*)&gamma[lane * 4];
            float4 b = *(const float4*)&beta[lane * 4];
            float4 o4;
            o4.x = (y.x - mu) * rs * g.x + b.x;
            o4.y = (y.y - mu) * rs * g.y + b.y;
            o4.z = (y.z - mu) * rs * g.z + b.z;
            o4.w = (y.w - mu) * rs * g.w + b.w;
            *(float4*)&out32[(n0 + row) * CC + lane * 4] = o4;
        }
    } else {
        #pragma unroll
        for (int im = 0; im < 2; im++)
            #pragma unroll
            for (int jn = 0; jn < 8; jn++) {
                int rl = wm * 32 + im * 16 + qm;
                int cl = wn * 64 + jn * 8 + qn;
                float2 bb = *(const float2*)&bias[cl];
                float2 lo = {c[im][jn][0] + bb.x, c[im][jn][1] + bb.y};
                float2 hi = {c[im][jn][2] + bb.x, c[im][jn][3] + bb.y};
                if (MODE == 0) {
                    *(float2*)&out32[(n0 + rl) * CC + cl]     = lo;
                    *(float2*)&out32[(n0 + rl + 8) * CC + cl] = hi;
                } else {
                    __nv_bfloat162 h0 = {__float2bfloat16_rn(lo.x), __float2bfloat16_rn(lo.y)};
                    __nv_bfloat162 h1 = {__float2bfloat16_rn(hi.x), __float2bfloat16_rn(hi.y)};
                    *(__nv_bfloat162*)&out16[(n0 + rl) * CC + cl]     = h0;
                    *(__nv_bfloat162*)&out16[(n0 + rl + 8) * CC + cl] = h1;
                }
            }
    }
}

__global__ __launch_bounds__(128) void qkv_mma_kernel(
        const float* __restrict__ bq, const float* __restrict__ bk,
        const float* __restrict__ bv) {
    int which = blockIdx.y;
    if (which == 0)
        mma_gemm_body<0>(g_xh, g_wh,           bq, nullptr, nullptr, nullptr, g_q, nullptr);
    else if (which == 1)
        mma_gemm_body<1>(g_xh, g_wh + CC*CC,   bk, nullptr, nullptr, nullptr, nullptr, g_kh);
    else
        mma_gemm_body<1>(g_xh, g_wh + 2*CC*CC, bv, nullptr, nullptr, nullptr, nullptr, g_vh);
}

__global__ __launch_bounds__(128) void out_mma_kernel(
        const float* __restrict__ bo, const float* __restrict__ x,
        const float* __restrict__ gamma, const float* __restrict__ beta,
        float* __restrict__ out) {
    mma_gemm_body<2>(g_ah, g_wh + 3*CC*CC, bo, x, gamma, beta, out, nullptr);
}

// ---------------------------------------------------------------------------
// 3) sparse attention (R11 staged design — best measured: 20.35us)
// ---------------------------------------------------------------------------
__global__ __launch_bounds__(128) void attn_kernel() {
    __shared__ int   nbr[NBR_CAP];
    __shared__ float ps[4][32];
    __shared__ float qs[4][32];
    __shared__ int   wsum[4];
    __shared__ int   s_deg;
    __shared__ __align__(16) unsigned ks[32][68];  // k rows: 256B data, stride 272B
    __shared__ __align__(16) unsigned vs[32][72];  // v rows: 256B data, stride 288B
    const int n    = blockIdx.x;
    const int t    = threadIdx.x;      // 0..127
    const int lane = t & 31;
    const int h    = t >> 5;           // warp == head

    qs[h][lane] = g_q[n*CC + h*32 + lane] * 0.17677669529663687f; // 1/sqrt(32)

    // --- build deduped neighbor list from bitmask row ---
    unsigned w = g_mask[(n << 7) + t];
    int c = __popc(w);
    int inc = c;
    #pragma unroll
    for (int o = 1; o < 32; o <<= 1) {
        int v = __shfl_up_sync(0xffffffffu, inc, o);
        if (lane >= o) inc += v;
    }
    if (lane == 31) wsum[h] = inc;
    __syncthreads();
    int base = 0;
    for (int i = 0; i < h; i++) base += wsum[i];
    int off = base + inc - c;
    int colbase = t << 5;
    while (w) {
        int b = __ffs(w) - 1;
        w &= w - 1;
        if (off < NBR_CAP) nbr[off] = colbase + b;
        off++;
    }
    if (t == 127) s_deg = (off < NBR_CAP) ? off : NBR_CAP;
    __syncthreads();
    const int deg = s_deg;             // >= 1 (self loops guaranteed)

    const int half = lane >> 4;
    const int dp   = lane & 15;
    const int ca   = half << 1;

    float M = -1e30f, l = 0.f;
    float2 accA = {0.f, 0.f}, accB = {0.f, 0.f};

    for (int j0 = 0; j0 < deg; j0 += 32) {
        const int nj = min(32, deg - j0);

        // ---- cooperative stage: 32 full k/v rows (clamped dup beyond nj) ----
        #pragma unroll
        for (int i = 0; i < 4; i++) {
            int r   = (h << 3) + (lane >> 3) + ((i >> 1) << 2);
            int idx = (lane & 7) + ((i & 1) << 3);
            int m   = nbr[min(j0 + r, deg - 1)];
            uint4 kv4 = ((const uint4*)g_kh)[(m << 4) + idx];
            uint4 vv4 = ((const uint4*)g_vh)[(m << 4) + idx];
            *(uint4*)&ks[r][idx << 2] = kv4;
            *(uint4*)&vs[r][idx << 2] = vv4;
        }
        __syncthreads();

        // ---- phase A: lane = neighbor, 32-dim dot from smem ----
        float s = -1e30f;
        if (lane < nj) {
            const unsigned* kr = &ks[lane][h << 4];
            float sv = 0.f;
            #pragma unroll
            for (int i = 0; i < 4; i++) {
                uint4 u = *(const uint4*)(kr + (i << 2));
                float2 f0 = __bfloat1622float2(*(__nv_bfloat162*)&u.x);
                float2 f1 = __bfloat1622float2(*(__nv_bfloat162*)&u.y);
                float2 f2 = __bfloat1622float2(*(__nv_bfloat162*)&u.z);
                float2 f3 = __bfloat1622float2(*(__nv_bfloat162*)&u.w);
                sv += qs[h][i*8+0]*f0.x + qs[h][i*8+1]*f0.y
                    + qs[h][i*8+2]*f1.x + qs[h][i*8+3]*f1.y
                    + qs[h][i*8+4]*f2.x + qs[h][i*8+5]*f2.y
                    + qs[h][i*8+6]*f3.x + qs[h][i*8+7]*f3.y;
            }
            s = sv;
        }

        // ---- phase B: chunk softmax ----
        float mx = s;
        #pragma unroll
        for (int o = 16; o; o >>= 1) mx = fmaxf(mx, __shfl_xor_sync(0xffffffffu, mx, o));
        float Mn = fmaxf(M, mx);
        float p = (lane < nj) ? __expf(s - Mn) : 0.f;
        ps[h][lane] = p;
        float psum = p;
        #pragma unroll
        for (int o = 16; o; o >>= 1) psum += __shfl_xor_sync(0xffffffffu, psum, o);
        float corr = __expf(M - Mn);
        l = l * corr + psum;
        accA.x *= corr; accA.y *= corr;
        accB.x *= corr; accB.y *= corr;
        M = Mn;
        __syncwarp();

        // ---- phase C: v from smem, 4 neighbors/iter, p=0 kills padded rows ----
        #pragma unroll
        for (int jj = 0; jj < 32; jj += 4) {
            int ra = jj + ca;
            int rb = jj + 1 + ca;
            float pa = ps[h][ra];
            float pb = ps[h][rb];
            float2 va = __bfloat1622float2(*(const __nv_bfloat162*)&vs[ra][(h << 4) + dp]);
            float2 vb = __bfloat1622float2(*(const __nv_bfloat162*)&vs[rb][(h << 4) + dp]);
            accA.x += pa * va.x; accA.y += pa * va.y;
            accB.x += pb * vb.x; accB.y += pb * vb.y;
        }
        __syncthreads();   // staging buffers reused next chunk
    }

    float ax = accA.x + accB.x;
    float ay = accA.y + accB.y;
    ax += __shfl_xor_sync(0xffffffffu, ax, 16);
    ay += __shfl_xor_sync(0xffffffffu, ay, 16);
    if (half == 0) {
        float rl = 1.f / l;
        __nv_bfloat162 hv = {__float2bfloat16_rn(ax * rl), __float2bfloat16_rn(ay * rl)};
        *(__nv_bfloat162*)&g_ah[n*CC + h*32 + dp*2] = hv;
    }
}

// ---------------------------------------------------------------------------
extern "C" void kernel_launch(void* const* d_in, const int* in_sizes, int n_in,
                              void* d_out, int out_size) {
    const float* x     = (const float*)d_in[0];
    const void*  ei    = d_in[1];
    const float* wq    = (const float*)d_in[2];
    const float* bq    = (const float*)d_in[3];
    const float* wk    = (const float*)d_in[4];
    const float* bk    = (const float*)d_in[5];
    const float* wv    = (const float*)d_in[6];
    const float* bv    = (const float*)d_in[7];
    const float* wo    = (const float*)d_in[8];
    const float* bo    = (const float*)d_in[9];
    const float* gamma = (const float*)d_in[10];
    const float* beta  = (const float*)d_in[11];
    float*       out   = (float*)d_out;
    const int n_elems = in_sizes[1];   // 2*E regardless of dtype
    const int E = n_elems / 2;
    const int SMEM_MMA = 17408 + 34816;  // As + Ws = 52224

    cudaFuncSetAttribute(qkv_mma_kernel, cudaFuncAttributeMaxDynamicSharedMemorySize, SMEM_MMA);
    cudaFuncSetAttribute(out_mma_kernel, cudaFuncAttributeMaxDynamicSharedMemorySize, SMEM_MMA);

    prep_kernel<<<512, 256>>>((const unsigned*)ei, n_elems);
    scatter_kernel<<<(E + 255) / 256, 256>>>(ei, E);
    cvt_kernel<<<(NC/4 + 4*CC*CC/4 + 255) / 256, 256>>>(x, wq, wk, wv, wo);
    qkv_mma_kernel<<<dim3(NN/64, 3), 128, SMEM_MMA>>>(bq, bk, bv);
    attn_kernel<<<NN, 128>>>();
    out_mma_kernel<<<NN/64, 128, SMEM_MMA>>>(bo, x, gamma, beta, out);
}